// round 15
// baseline (speedup 1.0000x reference)
#include <cuda_runtime.h>
#include <cuda_fp16.h>
#include <cstdint>
#include <cstddef>

// ---------------------------------------------------------------------------
// Problem constants
// ---------------------------------------------------------------------------
#define M_ROWS 512
#define N_OUT  8192
#define K_IN   8192

#define TILE_M 128
#define TILE_N 128
#define TILE_K 64                     // K elements per chunk
#define KSPLIT 8
#define K_UNIT (K_IN / KSPLIT)        // 1024
#define NCH    (K_UNIT / TILE_K)      // 16 chunks per unit
#define NUNITS (4 * KSPLIT * 64)      // 2048 units: mt x kq x nt
#define NSLOTS 296                    // 148 SMs x 2 CTAs
#define STAGES 3

#define A_STAGE_BYTES (TILE_M * TILE_K * 2)   // 16384 fp16, swizzled
#define B_STAGE_BYTES (TILE_N * TILE_K * 2)   // 16384 fp16, swizzled
#define STAGE_BYTES (A_STAGE_BYTES + B_STAGE_BYTES)
#define SMEM_TOTAL (STAGES * STAGE_BYTES)     // 98304

// ---------------------------------------------------------------------------
// Scratch (device globals: allocation-free rule)
// ---------------------------------------------------------------------------
__device__ __half g_xh[(size_t)M_ROWS * K_IN];               // 8 MB fp16 x
__device__ __half g_wh[(size_t)N_OUT * K_IN];                // 128 MB fp16 W
__device__ __half g_part[(size_t)KSPLIT * M_ROWS * N_OUT];   // 67 MB partials

// ---------------------------------------------------------------------------
// Helpers
// ---------------------------------------------------------------------------
__device__ __forceinline__ uint32_t smem_u32(const void* p) {
    uint32_t a;
    asm("{ .reg .u64 t; cvta.to.shared.u64 t, %1; cvt.u32.u64 %0, t; }"
        : "=r"(a) : "l"(p));
    return a;
}

__device__ __forceinline__ uint32_t sw128(uint32_t off) {
    return off ^ ((off >> 3) & 0x70);
}

__device__ __forceinline__ void cp_async16(uint32_t dst, const void* src) {
    asm volatile("cp.async.cg.shared.global [%0], [%1], 16;\n"
                 :: "r"(dst), "l"(src) : "memory");
}
#define CP_COMMIT() asm volatile("cp.async.commit_group;\n" ::: "memory")
#define CP_WAIT1()  asm volatile("cp.async.wait_group 1;\n" ::: "memory")

__device__ __forceinline__ void ldmatrix_x4(uint32_t* r, uint32_t addr) {
    asm volatile("ldmatrix.sync.aligned.m8n8.x4.shared.b16 {%0,%1,%2,%3}, [%4];\n"
                 : "=r"(r[0]), "=r"(r[1]), "=r"(r[2]), "=r"(r[3]) : "r"(addr));
}

__device__ __forceinline__ void mma16816(float* c, const uint32_t* a,
                                         const uint32_t* b) {
    asm volatile(
        "mma.sync.aligned.m16n8k16.row.col.f32.f16.f16.f32 "
        "{%0,%1,%2,%3}, {%4,%5,%6,%7}, {%8,%9}, {%0,%1,%2,%3};\n"
        : "+f"(c[0]), "+f"(c[1]), "+f"(c[2]), "+f"(c[3])
        : "r"(a[0]), "r"(a[1]), "r"(a[2]), "r"(a[3]), "r"(b[0]), "r"(b[1]));
}

// ---------------------------------------------------------------------------
// Kernel 1: x fp32 -> fp16
// ---------------------------------------------------------------------------
__global__ void __launch_bounds__(256) cvt_x_kernel(const float* __restrict__ x) {
    size_t t = (size_t)blockIdx.x * 256 + threadIdx.x;
    size_t base = t * 8;
    float4 a = *reinterpret_cast<const float4*>(x + base);
    float4 b = *reinterpret_cast<const float4*>(x + base + 4);
    __align__(16) __half h[8];
    h[0] = __float2half_rn(a.x); h[1] = __float2half_rn(a.y);
    h[2] = __float2half_rn(a.z); h[3] = __float2half_rn(a.w);
    h[4] = __float2half_rn(b.x); h[5] = __float2half_rn(b.y);
    h[6] = __float2half_rn(b.z); h[7] = __float2half_rn(b.w);
    *reinterpret_cast<uint4*>(g_xh + base) = *reinterpret_cast<uint4*>(h);
}

// ---------------------------------------------------------------------------
// Kernel 2: dequant W (int32-widened int8 * block scale) -> fp16
// ---------------------------------------------------------------------------
__global__ void __launch_bounds__(256) dequant_w_kernel(
    const int* __restrict__ wq, const float* __restrict__ ws) {
    size_t t = (size_t)blockIdx.x * 256 + threadIdx.x;
    size_t base = t * 8;
    int o = (int)(base >> 13);           // out feature
    int i = (int)(base & (K_IN - 1));    // in feature
    float s = ws[(o >> 7) * (K_IN / 128) + (i >> 7)];
    int4 a = *reinterpret_cast<const int4*>(wq + base);
    int4 b = *reinterpret_cast<const int4*>(wq + base + 4);
    __align__(16) __half h[8];
    h[0] = __float2half_rn(s * (float)a.x);
    h[1] = __float2half_rn(s * (float)a.y);
    h[2] = __float2half_rn(s * (float)a.z);
    h[3] = __float2half_rn(s * (float)a.w);
    h[4] = __float2half_rn(s * (float)b.x);
    h[5] = __float2half_rn(s * (float)b.y);
    h[6] = __float2half_rn(s * (float)b.z);
    h[7] = __float2half_rn(s * (float)b.w);
    *reinterpret_cast<uint4*>(g_wh + base) = *reinterpret_cast<uint4*>(h);
}

// ---------------------------------------------------------------------------
// Kernel 3: persistent fp16 GEMM (mma.sync), 3-stage pipeline kept hot
//   across unit boundaries. 296 CTAs, each runs a contiguous unit range.
//   unit u -> mt = u&3, kq = (u>>2)&7, nt = u>>5.
// ---------------------------------------------------------------------------
__global__ void __launch_bounds__(256, 2) gemm_kernel(void) {
    extern __shared__ char smem[];
    uint32_t sb = smem_u32(smem);
    int tid = threadIdx.x;
    int lid = tid & 31;
    int wid = tid >> 5;
    int wm = wid >> 1, wn = wid & 1;          // 4x2 warp grid
    int m_warp = wm * 32, n_warp = wn * 64;   // warp tile 32m x 64n

    int b = blockIdx.x;
    int uStart = (b * NUNITS) / NSLOTS;
    int uEnd   = ((b + 1) * NUNITS) / NSLOTS;
    int nChunks = (uEnd - uStart) * NCH;

    const __half* xh = g_xh;
    const __half* wh = g_wh;

    float acc[2][8][4];
#pragma unroll
    for (int mi = 0; mi < 2; ++mi)
#pragma unroll
        for (int ni = 0; ni < 8; ++ni)
#pragma unroll
            for (int j = 0; j < 4; ++j) acc[mi][ni][j] = 0.f;

    // load global-chunk gc into stage slot (unit mapping inlined)
#define LOAD_CHUNK(slot, gc_) do {                                            \
    int _u = uStart + ((gc_) >> 4);                                           \
    int _m0 = (_u & 3) * TILE_M;                                              \
    int _n0 = (_u >> 5) * TILE_N;                                             \
    int _k0 = (((_u >> 2) & 7) << 10) + (((gc_) & 15) * TILE_K);              \
    uint32_t ab = sb + (uint32_t)(slot) * STAGE_BYTES;                        \
    uint32_t bb = ab + A_STAGE_BYTES;                                         \
    _Pragma("unroll")                                                         \
    for (int i = 0; i < 4; ++i) {                                             \
        int seg = tid + i * 256;                                              \
        int row = seg >> 3, c = seg & 7;                                      \
        cp_async16(ab + sw128((uint32_t)row * 128 + c * 16),                  \
                   xh + (size_t)(_m0 + row) * K_IN + _k0 + c * 8);            \
        cp_async16(bb + sw128((uint32_t)row * 128 + c * 16),                  \
                   wh + (size_t)(_n0 + row) * K_IN + _k0 + c * 8);            \
    }                                                                         \
} while (0)

    // ---- prologue: first two chunks in flight ----
    LOAD_CHUNK(0, 0);
    CP_COMMIT();
    LOAD_CHUNK(1, 1);
    CP_COMMIT();
    CP_WAIT1();              // chunk 0 landed
    __syncthreads();

    // ---- persistent main loop over the CTA's whole chunk stream ----
    int cur = 0, nxt2 = 2;
#pragma unroll 1
    for (int gc = 0; gc < nChunks; ++gc) {
        if (gc + 2 < nChunks) LOAD_CHUNK(nxt2, gc + 2);
        CP_COMMIT();

        uint32_t aBase = sb + (uint32_t)cur * STAGE_BYTES;
        uint32_t bBase = aBase + A_STAGE_BYTES;

#pragma unroll
        for (int ks = 0; ks < 4; ++ks) {
            uint32_t af[2][4];
#pragma unroll
            for (int mi = 0; mi < 2; ++mi) {
                uint32_t off = (uint32_t)(m_warp + mi * 16 + (lid & 15)) * 128
                             + ks * 32 + ((lid >> 4) << 4);
                ldmatrix_x4(af[mi], aBase + sw128(off));
            }
            uint32_t bf[8][2];
#pragma unroll
            for (int ntl = 0; ntl < 4; ++ntl) {
                uint32_t r[4];
                uint32_t off = (uint32_t)(n_warp + ntl * 16 + (lid & 7)
                                          + ((lid >> 4) << 3)) * 128
                             + ks * 32 + (((lid >> 3) & 1) << 4);
                ldmatrix_x4(r, bBase + sw128(off));
                bf[2 * ntl][0] = r[0]; bf[2 * ntl][1] = r[1];
                bf[2 * ntl + 1][0] = r[2]; bf[2 * ntl + 1][1] = r[3];
            }
#pragma unroll
            for (int mi = 0; mi < 2; ++mi)
#pragma unroll
                for (int ni = 0; ni < 8; ++ni)
                    mma16816(acc[mi][ni], af[mi], bf[ni]);
        }

        // ---- unit boundary: drain accumulators, keep pipeline hot ----
        if ((gc & (NCH - 1)) == NCH - 1) {
            int u = uStart + (gc >> 4);
            int m0 = (u & 3) * TILE_M;
            int n0 = (u >> 5) * TILE_N;
            int kq = (u >> 2) & 7;
            __half* pout = g_part + (size_t)kq * ((size_t)M_ROWS * N_OUT);
#pragma unroll
            for (int mi = 0; mi < 2; ++mi) {
#pragma unroll
                for (int ni = 0; ni < 8; ++ni) {
                    int row = m0 + m_warp + mi * 16 + (lid >> 2);
                    int col = n0 + n_warp + ni * 8 + ((lid & 3) << 1);
                    __half2 v0 = __floats2half2_rn(acc[mi][ni][0], acc[mi][ni][1]);
                    __half2 v1 = __floats2half2_rn(acc[mi][ni][2], acc[mi][ni][3]);
                    *reinterpret_cast<__half2*>(pout + (size_t)row * N_OUT + col) = v0;
                    *reinterpret_cast<__half2*>(pout + (size_t)(row + 8) * N_OUT + col) = v1;
#pragma unroll
                    for (int j = 0; j < 4; ++j) acc[mi][ni][j] = 0.f;
                }
            }
        }

        CP_WAIT1();          // next chunk landed
        __syncthreads();

        cur = (cur == STAGES - 1) ? 0 : cur + 1;
        nxt2 = (nxt2 == STAGES - 1) ? 0 : nxt2 + 1;
    }
}

// ---------------------------------------------------------------------------
// Kernel 4: reduce 8 fp16 partials -> fp32 out
// ---------------------------------------------------------------------------
__global__ void __launch_bounds__(256) reduce_kernel(float* __restrict__ out) {
    size_t t = (size_t)blockIdx.x * 256 + threadIdx.x;
    size_t base = t * 8;
    const size_t SZ = (size_t)M_ROWS * N_OUT;
    float r[8];
#pragma unroll
    for (int j = 0; j < 8; ++j) r[j] = 0.f;
#pragma unroll
    for (int kq = 0; kq < KSPLIT; ++kq) {
        uint4 v = *reinterpret_cast<const uint4*>(g_part + kq * SZ + base);
        const __half2* h = reinterpret_cast<const __half2*>(&v);
#pragma unroll
        for (int j = 0; j < 4; ++j) {
            float2 f = __half22float2(h[j]);
            r[2 * j] += f.x;
            r[2 * j + 1] += f.y;
        }
    }
    float4 o0 = make_float4(r[0], r[1], r[2], r[3]);
    float4 o1 = make_float4(r[4], r[5], r[6], r[7]);
    *reinterpret_cast<float4*>(out + base) = o0;
    *reinterpret_cast<float4*>(out + base + 4) = o1;
}

// ---------------------------------------------------------------------------
// Launch
// ---------------------------------------------------------------------------
extern "C" void kernel_launch(void* const* d_in, const int* in_sizes, int n_in,
                              void* d_out, int out_size) {
    const float* x  = (const float*)d_in[0];
    const int*   wq = (const int*)d_in[1];     // int8 widened to int32 by harness
    const float* ws = (const float*)d_in[2];
    float* out = (float*)d_out;

    cvt_x_kernel<<<2048, 256>>>(x);
    dequant_w_kernel<<<32768, 256>>>(wq, ws);

    cudaFuncSetAttribute(gemm_kernel,
                         cudaFuncAttributeMaxDynamicSharedMemorySize, SMEM_TOTAL);
    // persistent: one CTA per residency slot
    gemm_kernel<<<NSLOTS, 256, SMEM_TOTAL>>>();

    // 512*8192 / 8 / 256 = 2048 blocks
    reduce_kernel<<<2048, 256>>>(out);
}

// round 16
// speedup vs baseline: 1.0912x; 1.0912x over previous
#include <cuda_runtime.h>
#include <cuda_fp16.h>
#include <cstdint>
#include <cstddef>

// ---------------------------------------------------------------------------
// Problem constants
// ---------------------------------------------------------------------------
#define M_ROWS 512
#define N_OUT  8192
#define K_IN   8192

#define TILE_M 128
#define TILE_N 128
#define TILE_K 64                     // K elements per stage
#define KSPLIT 4
#define K_UNIT (K_IN / KSPLIT)        // 2048
#define NCH    (K_UNIT / TILE_K)      // 32 chunks per unit
#define STAGES 3

#define A_STAGE_BYTES (TILE_M * TILE_K * 2)   // 16384 fp16, swizzled
#define B_STAGE_BYTES (TILE_N * TILE_K * 2)   // 16384 fp16, swizzled
#define STAGE_BYTES (A_STAGE_BYTES + B_STAGE_BYTES)
#define SMEM_TOTAL (STAGES * STAGE_BYTES)     // 98304

// ---------------------------------------------------------------------------
// Scratch (device globals: allocation-free rule)
// ---------------------------------------------------------------------------
__device__ __half g_xh[(size_t)M_ROWS * K_IN];               // 8 MB fp16 x
__device__ __half g_wh[(size_t)N_OUT * K_IN];                // 128 MB fp16 W
__device__ __half g_part[(size_t)KSPLIT * M_ROWS * N_OUT];   // 33.5 MB partials

// ---------------------------------------------------------------------------
// Helpers
// ---------------------------------------------------------------------------
__device__ __forceinline__ uint32_t smem_u32(const void* p) {
    uint32_t a;
    asm("{ .reg .u64 t; cvta.to.shared.u64 t, %1; cvt.u32.u64 %0, t; }"
        : "=r"(a) : "l"(p));
    return a;
}

__device__ __forceinline__ uint32_t sw128(uint32_t off) {
    return off ^ ((off >> 3) & 0x70);
}

__device__ __forceinline__ void cp_async16(uint32_t dst, const void* src) {
    asm volatile("cp.async.cg.shared.global [%0], [%1], 16;\n"
                 :: "r"(dst), "l"(src) : "memory");
}
#define CP_COMMIT() asm volatile("cp.async.commit_group;\n" ::: "memory")
#define CP_WAIT1()  asm volatile("cp.async.wait_group 1;\n" ::: "memory")

__device__ __forceinline__ void ldmatrix_x4(uint32_t* r, uint32_t addr) {
    asm volatile("ldmatrix.sync.aligned.m8n8.x4.shared.b16 {%0,%1,%2,%3}, [%4];\n"
                 : "=r"(r[0]), "=r"(r[1]), "=r"(r[2]), "=r"(r[3]) : "r"(addr));
}

__device__ __forceinline__ void mma16816(float* c, const uint32_t* a,
                                         const uint32_t* b) {
    asm volatile(
        "mma.sync.aligned.m16n8k16.row.col.f32.f16.f16.f32 "
        "{%0,%1,%2,%3}, {%4,%5,%6,%7}, {%8,%9}, {%0,%1,%2,%3};\n"
        : "+f"(c[0]), "+f"(c[1]), "+f"(c[2]), "+f"(c[3])
        : "r"(a[0]), "r"(a[1]), "r"(a[2]), "r"(a[3]), "r"(b[0]), "r"(b[1]));
}

// ---------------------------------------------------------------------------
// Kernel 1: x fp32 -> fp16
// ---------------------------------------------------------------------------
__global__ void __launch_bounds__(256) cvt_x_kernel(const float* __restrict__ x) {
    size_t t = (size_t)blockIdx.x * 256 + threadIdx.x;
    size_t base = t * 8;
    float4 a = *reinterpret_cast<const float4*>(x + base);
    float4 b = *reinterpret_cast<const float4*>(x + base + 4);
    __align__(16) __half h[8];
    h[0] = __float2half_rn(a.x); h[1] = __float2half_rn(a.y);
    h[2] = __float2half_rn(a.z); h[3] = __float2half_rn(a.w);
    h[4] = __float2half_rn(b.x); h[5] = __float2half_rn(b.y);
    h[6] = __float2half_rn(b.z); h[7] = __float2half_rn(b.w);
    *reinterpret_cast<uint4*>(g_xh + base) = *reinterpret_cast<uint4*>(h);
}

// ---------------------------------------------------------------------------
// Kernel 2: dequant W (int32-widened int8 * block scale) -> fp16.
//   __ldcs on weight reads: single-use stream, evict-first in L2.
// ---------------------------------------------------------------------------
__global__ void __launch_bounds__(256) dequant_w_kernel(
    const int* __restrict__ wq, const float* __restrict__ ws) {
    size_t t = (size_t)blockIdx.x * 256 + threadIdx.x;
    size_t base = t * 8;
    int o = (int)(base >> 13);           // out feature
    int i = (int)(base & (K_IN - 1));    // in feature
    float s = ws[(o >> 7) * (K_IN / 128) + (i >> 7)];
    int4 a = __ldcs(reinterpret_cast<const int4*>(wq + base));
    int4 b = __ldcs(reinterpret_cast<const int4*>(wq + base + 4));
    __align__(16) __half h[8];
    h[0] = __float2half_rn(s * (float)a.x);
    h[1] = __float2half_rn(s * (float)a.y);
    h[2] = __float2half_rn(s * (float)a.z);
    h[3] = __float2half_rn(s * (float)a.w);
    h[4] = __float2half_rn(s * (float)b.x);
    h[5] = __float2half_rn(s * (float)b.y);
    h[6] = __float2half_rn(s * (float)b.z);
    h[7] = __float2half_rn(s * (float)b.w);
    *reinterpret_cast<uint4*>(g_wh + base) = *reinterpret_cast<uint4*>(h);
}

// ---------------------------------------------------------------------------
// Kernel 3: fp16 GEMM (mma.sync), 3-stage cp.async pipeline, 2 CTAs/SM,
//   split-K x4. Byte-identical to the measured-best R11 kernel.
//   grid = 1024: bid -> (mt 0..3 fastest, kq 0..3, nt 0..63)
// ---------------------------------------------------------------------------
__global__ void __launch_bounds__(256, 2) gemm_kernel(void) {
    extern __shared__ char smem[];
    uint32_t sb = smem_u32(smem);
    int tid = threadIdx.x;
    int lid = tid & 31;
    int wid = tid >> 5;
    int wm = wid >> 1, wn = wid & 1;          // 4x2 warp grid
    int m_warp = wm * 32, n_warp = wn * 64;   // warp tile 32m x 64n

    int bid = blockIdx.x;
    int mt = bid & 3;
    int kq = (bid >> 2) & 3;
    int nt = bid >> 4;
    int m0 = mt * TILE_M;
    int n0 = nt * TILE_N;
    int kbase = kq * K_UNIT;

    const __half* xh = g_xh;
    const __half* wh = g_wh;

    float acc[2][8][4];
#pragma unroll
    for (int mi = 0; mi < 2; ++mi)
#pragma unroll
        for (int ni = 0; ni < 8; ++ni)
#pragma unroll
            for (int j = 0; j < 4; ++j) acc[mi][ni][j] = 0.f;

#define LOAD_STAGE(slot, chunk) do {                                          \
    int k0h = kbase + (chunk) * TILE_K;                                       \
    uint32_t ab = sb + (uint32_t)(slot) * STAGE_BYTES;                        \
    uint32_t bb = ab + A_STAGE_BYTES;                                         \
    _Pragma("unroll")                                                         \
    for (int i = 0; i < 4; ++i) {                                             \
        int seg = tid + i * 256;                                              \
        int row = seg >> 3, c = seg & 7;                                      \
        cp_async16(ab + sw128((uint32_t)row * 128 + c * 16),                  \
                   xh + (size_t)(m0 + row) * K_IN + k0h + c * 8);             \
        cp_async16(bb + sw128((uint32_t)row * 128 + c * 16),                  \
                   wh + (size_t)(n0 + row) * K_IN + k0h + c * 8);             \
    }                                                                         \
} while (0)

    // ---- prologue: stages 0,1 in flight ----
    LOAD_STAGE(0, 0);
    CP_COMMIT();
    LOAD_STAGE(1, 1);
    CP_COMMIT();
    CP_WAIT1();              // stage 0 landed
    __syncthreads();

    // ---- main loop ----
    int cur = 0, nxt2 = 2;
#pragma unroll 1
    for (int it = 0; it < NCH; ++it) {
        if (it + 2 < NCH) LOAD_STAGE(nxt2, it + 2);
        CP_COMMIT();

        uint32_t aBase = sb + (uint32_t)cur * STAGE_BYTES;
        uint32_t bBase = aBase + A_STAGE_BYTES;

#pragma unroll
        for (int ks = 0; ks < 4; ++ks) {
            uint32_t af[2][4];
#pragma unroll
            for (int mi = 0; mi < 2; ++mi) {
                uint32_t off = (uint32_t)(m_warp + mi * 16 + (lid & 15)) * 128
                             + ks * 32 + ((lid >> 4) << 4);
                ldmatrix_x4(af[mi], aBase + sw128(off));
            }
            uint32_t bf[8][2];
#pragma unroll
            for (int ntl = 0; ntl < 4; ++ntl) {
                uint32_t r[4];
                uint32_t off = (uint32_t)(n_warp + ntl * 16 + (lid & 7)
                                          + ((lid >> 4) << 3)) * 128
                             + ks * 32 + (((lid >> 3) & 1) << 4);
                ldmatrix_x4(r, bBase + sw128(off));
                bf[2 * ntl][0] = r[0]; bf[2 * ntl][1] = r[1];
                bf[2 * ntl + 1][0] = r[2]; bf[2 * ntl + 1][1] = r[3];
            }
#pragma unroll
            for (int mi = 0; mi < 2; ++mi)
#pragma unroll
                for (int ni = 0; ni < 8; ++ni)
                    mma16816(acc[mi][ni], af[mi], bf[ni]);
        }

        CP_WAIT1();          // next stage landed
        __syncthreads();

        cur = (cur == STAGES - 1) ? 0 : cur + 1;
        nxt2 = (nxt2 == STAGES - 1) ? 0 : nxt2 + 1;
    }

    // ---- epilogue: fp16 partials -> g_part[kq] ----
    __half* pout = g_part + (size_t)kq * ((size_t)M_ROWS * N_OUT);
#pragma unroll
    for (int mi = 0; mi < 2; ++mi) {
#pragma unroll
        for (int ni = 0; ni < 8; ++ni) {
            int row = m0 + m_warp + mi * 16 + (lid >> 2);
            int col = n0 + n_warp + ni * 8 + ((lid & 3) << 1);
            __half2 v0 = __floats2half2_rn(acc[mi][ni][0], acc[mi][ni][1]);
            __half2 v1 = __floats2half2_rn(acc[mi][ni][2], acc[mi][ni][3]);
            *reinterpret_cast<__half2*>(pout + (size_t)row * N_OUT + col) = v0;
            *reinterpret_cast<__half2*>(pout + (size_t)(row + 8) * N_OUT + col) = v1;
        }
    }
}

// ---------------------------------------------------------------------------
// Kernel 4: reduce 4 fp16 partials -> fp32 out (16 outputs/thread, MLP 8)
// ---------------------------------------------------------------------------
__global__ void __launch_bounds__(256) reduce_kernel(float* __restrict__ out) {
    size_t t = (size_t)blockIdx.x * 256 + threadIdx.x;
    size_t base = t * 16;
    const size_t SZ = (size_t)M_ROWS * N_OUT;
    float r[16];
#pragma unroll
    for (int j = 0; j < 16; ++j) r[j] = 0.f;
#pragma unroll
    for (int kq = 0; kq < KSPLIT; ++kq) {
        uint4 v0 = *reinterpret_cast<const uint4*>(g_part + kq * SZ + base);
        uint4 v1 = *reinterpret_cast<const uint4*>(g_part + kq * SZ + base + 8);
        const __half2* h0 = reinterpret_cast<const __half2*>(&v0);
        const __half2* h1 = reinterpret_cast<const __half2*>(&v1);
#pragma unroll
        for (int j = 0; j < 4; ++j) {
            float2 f0 = __half22float2(h0[j]);
            float2 f1 = __half22float2(h1[j]);
            r[2 * j]     += f0.x;
            r[2 * j + 1] += f0.y;
            r[8 + 2 * j]     += f1.x;
            r[8 + 2 * j + 1] += f1.y;
        }
    }
#pragma unroll
    for (int j = 0; j < 16; j += 4) {
        float4 o = make_float4(r[j], r[j + 1], r[j + 2], r[j + 3]);
        *reinterpret_cast<float4*>(out + base + j) = o;
    }
}

// ---------------------------------------------------------------------------
// Launch
// ---------------------------------------------------------------------------
extern "C" void kernel_launch(void* const* d_in, const int* in_sizes, int n_in,
                              void* d_out, int out_size) {
    const float* x  = (const float*)d_in[0];
    const int*   wq = (const int*)d_in[1];     // int8 widened to int32 by harness
    const float* ws = (const float*)d_in[2];
    float* out = (float*)d_out;

    cvt_x_kernel<<<2048, 256>>>(x);
    dequant_w_kernel<<<32768, 256>>>(wq, ws);

    cudaFuncSetAttribute(gemm_kernel,
                         cudaFuncAttributeMaxDynamicSharedMemorySize, SMEM_TOTAL);
    // 1024 units: 4 mt (fastest) x 4 kq x 64 nt
    gemm_kernel<<<1024, 256, SMEM_TOTAL>>>();

    // 512*8192 / 16 / 256 = 1024 blocks
    reduce_kernel<<<1024, 256>>>(out);
}